// round 4
// baseline (speedup 1.0000x reference)
#include <cuda_runtime.h>
#include <cstdint>

#define D_   2048
#define I_   1024
#define E_   32
#define K_   8
#define T_   8192
#define CAP  69632      // 65536 rows + 32 experts * 128 padding, multiple of 128
#define BM   128
#define BN   64
#define BKK  16

// ---------------- device scratch (static: no allocations allowed) ----------------
__device__ float    g_logits[(size_t)T_ * E_];
__device__ float    g_probs_sum[E_];
__device__ int      g_cnt[E_];
__device__ int      g_cnt2[E_];
__device__ int      g_base[E_ + 1];
__device__ int      g_topi[T_ * K_];
__device__ float    g_topw[T_ * K_];
__device__ int      g_tok[CAP];
__device__ float    g_wgt[CAP];
__device__ float    g_H[(size_t)CAP * I_];   // ~285 MB scratch for silu(xWg)*(xWu)*w

// ---------------- helpers ----------------
__device__ __forceinline__ unsigned f2tf(float f) {
    unsigned u;
    asm("cvt.rna.tf32.f32 %0, %1;" : "=r"(u) : "f"(f));
    return u;
}

__device__ __forceinline__ void mma_tf32(float c[4], const unsigned a[4], const unsigned b[2]) {
    asm volatile(
        "mma.sync.aligned.m16n8k8.row.col.f32.tf32.tf32.f32 "
        "{%0,%1,%2,%3}, {%4,%5,%6,%7}, {%8,%9}, {%0,%1,%2,%3};\n"
        : "+f"(c[0]), "+f"(c[1]), "+f"(c[2]), "+f"(c[3])
        : "r"(a[0]), "r"(a[1]), "r"(a[2]), "r"(a[3]), "r"(b[0]), "r"(b[1]));
}

// ---------------- small kernels ----------------
__global__ void init_k() {
    int i = threadIdx.x;
    if (i < E_) { g_cnt[i] = 0; g_cnt2[i] = 0; g_probs_sum[i] = 0.f; }
}

__global__ void fill_k() {
    int i = blockIdx.x * blockDim.x + threadIdx.x;
    if (i < CAP) { g_tok[i] = -1; g_wgt[i] = 0.f; }
}

// logits = X (T x D) @ Wgate (D x E), fp32 exact-ish
__global__ __launch_bounds__(256) void router_gemm_k(const float* __restrict__ x,
                                                     const float* __restrict__ Wgate) {
    __shared__ float Xs[64][65];
    __shared__ float Ws[64][32];
    int tid = threadIdx.x;
    int tok0 = blockIdx.x * 64;
    int e  = tid & 31;
    int tl = tid >> 5;   // 0..7
    float acc[8];
#pragma unroll
    for (int j = 0; j < 8; j++) acc[j] = 0.f;

    for (int d0 = 0; d0 < D_; d0 += 64) {
        __syncthreads();
#pragma unroll
        for (int p = 0; p < 4; p++) {
            int s = tid + p * 256;          // 1024 float4 slots
            int row = s >> 4, cg = s & 15;
            float4 v = *(const float4*)(x + (size_t)(tok0 + row) * D_ + d0 + cg * 4);
            Xs[row][cg * 4 + 0] = v.x; Xs[row][cg * 4 + 1] = v.y;
            Xs[row][cg * 4 + 2] = v.z; Xs[row][cg * 4 + 3] = v.w;
        }
#pragma unroll
        for (int p = 0; p < 2; p++) {
            int s = tid + p * 256;          // 512 float4 slots
            int row = s >> 3, cg = s & 7;
            float4 v = *(const float4*)(Wgate + (size_t)(d0 + row) * E_ + cg * 4);
            Ws[row][cg * 4 + 0] = v.x; Ws[row][cg * 4 + 1] = v.y;
            Ws[row][cg * 4 + 2] = v.z; Ws[row][cg * 4 + 3] = v.w;
        }
        __syncthreads();
#pragma unroll 8
        for (int d = 0; d < 64; d++) {
            float w = Ws[d][e];
#pragma unroll
            for (int j = 0; j < 8; j++) acc[j] += Xs[tl + 8 * j][d] * w;
        }
    }
#pragma unroll
    for (int j = 0; j < 8; j++)
        g_logits[(size_t)(tok0 + tl + 8 * j) * E_ + e] = acc[j];
}

// per-token: full softmax (aux), top-8 select + softmax over top-8
__global__ __launch_bounds__(256) void topk_k() {
    int t = blockIdx.x * 8 + (threadIdx.x >> 5);
    int lane = threadIdx.x & 31;
    float l = g_logits[(size_t)t * E_ + lane];

    // full softmax for aux loss
    float m = l;
#pragma unroll
    for (int off = 16; off; off >>= 1) m = fmaxf(m, __shfl_xor_sync(0xffffffffu, m, off));
    float p = __expf(l - m);
    float s = p;
#pragma unroll
    for (int off = 16; off; off >>= 1) s += __shfl_xor_sync(0xffffffffu, s, off);
    atomicAdd(&g_probs_sum[lane], p / s);

    // iterative warp argmax top-8 (tie-break: lower index)
    bool sel = false;
    float vals[K_]; int idxs[K_];
#pragma unroll
    for (int k = 0; k < K_; k++) {
        float bv = sel ? -3.4e38f : l;
        int   bi = lane;
#pragma unroll
        for (int off = 16; off; off >>= 1) {
            float ov = __shfl_xor_sync(0xffffffffu, bv, off);
            int   oi = __shfl_xor_sync(0xffffffffu, bi, off);
            if (ov > bv || (ov == bv && oi < bi)) { bv = ov; bi = oi; }
        }
        if (lane == bi) sel = true;
        vals[k] = bv; idxs[k] = bi;
    }
    // softmax over the 8 selected (vals[0] is the max)
    float ssum = 0.f;
    float w[K_];
#pragma unroll
    for (int k = 0; k < K_; k++) { w[k] = __expf(vals[k] - vals[0]); ssum += w[k]; }
    if (lane == 0) {
        float inv = 1.f / ssum;
#pragma unroll
        for (int k = 0; k < K_; k++) {
            g_topi[t * K_ + k] = idxs[k];
            g_topw[t * K_ + k] = w[k] * inv;
            atomicAdd(&g_cnt[idxs[k]], 1);
        }
    }
}

__global__ void prefix_k() {
    if (threadIdx.x == 0) {
        int b = 0;
        for (int e = 0; e < E_; e++) {
            g_base[e] = b;
            b += ((g_cnt[e] + BM - 1) / BM) * BM;   // 128-align per expert
        }
        g_base[E_] = b;
    }
}

__global__ void assign_k() {
    int i = blockIdx.x * blockDim.x + threadIdx.x;
    if (i < T_ * K_) {
        int e = g_topi[i];
        int p = atomicAdd(&g_cnt2[e], 1);
        int s = g_base[e] + p;
        g_tok[s] = i >> 3;       // token id
        g_wgt[s] = g_topw[i];
    }
}

// ---------------- GEMM1: H[row] = silu(x@Wg) * (x@Wu) * w   (tf32 MMA) ----------------
__global__ __launch_bounds__(256) void gemm1_k(const float* __restrict__ x,
                                               const float* __restrict__ Wg,
                                               const float* __restrict__ Wu) {
    int r0 = blockIdx.x * BM;
    int total = g_base[E_];
    if (r0 >= total) return;
    int n0 = blockIdx.y * BN;

    int e = 0;
#pragma unroll 1
    for (int i = 0; i < E_; i++) {
        if (r0 >= g_base[i] && r0 < g_base[i + 1]) { e = i; break; }
    }

    __shared__ unsigned As[BM * 20];   // stride 20: conflict-free A frag loads
    __shared__ unsigned Bg[BKK * 72];  // stride 72: conflict-free B frag loads
    __shared__ unsigned Bu[BKK * 72];
    __shared__ int Ts[BM];

    int tid = threadIdx.x;
    if (tid < BM) Ts[tid] = g_tok[r0 + tid];

    const float* wgE = Wg + (size_t)e * D_ * I_;
    const float* wuE = Wu + (size_t)e * D_ * I_;

    float cg_[2][4][4], cu_[2][4][4];
#pragma unroll
    for (int a = 0; a < 2; a++)
#pragma unroll
        for (int b = 0; b < 4; b++)
#pragma unroll
            for (int c = 0; c < 4; c++) { cg_[a][b][c] = 0.f; cu_[a][b][c] = 0.f; }

    int lane = tid & 31, warp = tid >> 5;
    int wm = warp >> 1, wn = warp & 1;   // 4x2 warp grid: 32x32 per warp

    for (int k0 = 0; k0 < D_; k0 += BKK) {
        __syncthreads();
#pragma unroll
        for (int p = 0; p < 2; p++) {                 // A: 512 float4 slots
            int s = tid + p * 256;
            int row = s >> 2, cgp = s & 3;
            int t = Ts[row];
            float4 v = make_float4(0.f, 0.f, 0.f, 0.f);
            if (t >= 0) v = *(const float4*)(x + (size_t)t * D_ + k0 + cgp * 4);
            unsigned* dst = &As[row * 20 + cgp * 4];
            dst[0] = f2tf(v.x); dst[1] = f2tf(v.y); dst[2] = f2tf(v.z); dst[3] = f2tf(v.w);
        }
        {                                             // B: 256 float4 slots each
            int row = tid >> 4, cgp = tid & 15;
            size_t off = (size_t)(k0 + row) * I_ + n0 + cgp * 4;
            float4 vg = *(const float4*)(wgE + off);
            float4 vu = *(const float4*)(wuE + off);
            unsigned* dg = &Bg[row * 72 + cgp * 4];
            dg[0] = f2tf(vg.x); dg[1] = f2tf(vg.y); dg[2] = f2tf(vg.z); dg[3] = f2tf(vg.w);
            unsigned* du = &Bu[row * 72 + cgp * 4];
            du[0] = f2tf(vu.x); du[1] = f2tf(vu.y); du[2] = f2tf(vu.z); du[3] = f2tf(vu.w);
        }
        __syncthreads();
#pragma unroll
        for (int kk = 0; kk < BKK; kk += 8) {
            unsigned a[2][4];
#pragma unroll
            for (int mf = 0; mf < 2; mf++) {
                int ar = wm * 32 + mf * 16 + (lane >> 2);
                int ak = kk + (lane & 3);
                a[mf][0] = As[ar * 20 + ak];
                a[mf][1] = As[(ar + 8) * 20 + ak];
                a[mf][2] = As[ar * 20 + ak + 4];
                a[mf][3] = As[(ar + 8) * 20 + ak + 4];
            }
            unsigned bg[4][2], bu[4][2];
#pragma unroll
            for (int nf = 0; nf < 4; nf++) {
                int bn = wn * 32 + nf * 8 + (lane >> 2);
                int bk = kk + (lane & 3);
                bg[nf][0] = Bg[bk * 72 + bn];
                bg[nf][1] = Bg[(bk + 4) * 72 + bn];
                bu[nf][0] = Bu[bk * 72 + bn];
                bu[nf][1] = Bu[(bk + 4) * 72 + bn];
            }
#pragma unroll
            for (int mf = 0; mf < 2; mf++)
#pragma unroll
                for (int nf = 0; nf < 4; nf++) {
                    mma_tf32(cg_[mf][nf], a[mf], bg[nf]);
                    mma_tf32(cu_[mf][nf], a[mf], bu[nf]);
                }
        }
    }

    // epilogue: silu(g)*u * routing-weight -> H
#pragma unroll
    for (int mf = 0; mf < 2; mf++) {
        int lr = wm * 32 + mf * 16 + (lane >> 2);
        float wlo = g_wgt[r0 + lr];
        float whi = g_wgt[r0 + lr + 8];
        size_t rowlo = (size_t)(r0 + lr) * I_;
        size_t rowhi = rowlo + (size_t)8 * I_;
#pragma unroll
        for (int nf = 0; nf < 4; nf++) {
            int c = n0 + wn * 32 + nf * 8 + 2 * (lane & 3);
            float g0 = cg_[mf][nf][0], g1 = cg_[mf][nf][1];
            float g2 = cg_[mf][nf][2], g3 = cg_[mf][nf][3];
            float u0 = cu_[mf][nf][0], u1 = cu_[mf][nf][1];
            float u2 = cu_[mf][nf][2], u3 = cu_[mf][nf][3];
            g_H[rowlo + c    ] = g0 / (1.f + __expf(-g0)) * u0 * wlo;
            g_H[rowlo + c + 1] = g1 / (1.f + __expf(-g1)) * u1 * wlo;
            g_H[rowhi + c    ] = g2 / (1.f + __expf(-g2)) * u2 * whi;
            g_H[rowhi + c + 1] = g3 / (1.f + __expf(-g3)) * u3 * whi;
        }
    }
}

// ---------------- GEMM2: out[token] += H @ Wd   (tf32 MMA + atomic scatter) ----------------
__global__ __launch_bounds__(256) void gemm2_k(const float* __restrict__ Wd,
                                               float* __restrict__ out) {
    int r0 = blockIdx.x * BM;
    int total = g_base[E_];
    if (r0 >= total) return;
    int n0 = blockIdx.y * BN;

    int e = 0;
#pragma unroll 1
    for (int i = 0; i < E_; i++) {
        if (r0 >= g_base[i] && r0 < g_base[i + 1]) { e = i; break; }
    }

    __shared__ unsigned As[BM * 20];
    __shared__ unsigned Bs[BKK * 72];
    __shared__ int Ts[BM];

    int tid = threadIdx.x;
    if (tid < BM) Ts[tid] = g_tok[r0 + tid];

    const float* wdE = Wd + (size_t)e * I_ * D_;

    float acc[2][4][4];
#pragma unroll
    for (int a = 0; a < 2; a++)
#pragma unroll
        for (int b = 0; b < 4; b++)
#pragma unroll
            for (int c = 0; c < 4; c++) acc[a][b][c] = 0.f;

    int lane = tid & 31, warp = tid >> 5;
    int wm = warp >> 1, wn = warp & 1;

    for (int k0 = 0; k0 < I_; k0 += BKK) {
        __syncthreads();
#pragma unroll
        for (int p = 0; p < 2; p++) {
            int s = tid + p * 256;
            int row = s >> 2, cgp = s & 3;
            float4 v = *(const float4*)(g_H + (size_t)(r0 + row) * I_ + k0 + cgp * 4);
            unsigned* dst = &As[row * 20 + cgp * 4];
            dst[0] = f2tf(v.x); dst[1] = f2tf(v.y); dst[2] = f2tf(v.z); dst[3] = f2tf(v.w);
        }
        {
            int row = tid >> 4, cgp = tid & 15;
            size_t off = (size_t)(k0 + row) * D_ + n0 + cgp * 4;
            float4 v = *(const float4*)(wdE + off);
            unsigned* db = &Bs[row * 72 + cgp * 4];
            db[0] = f2tf(v.x); db[1] = f2tf(v.y); db[2] = f2tf(v.z); db[3] = f2tf(v.w);
        }
        __syncthreads();
#pragma unroll
        for (int kk = 0; kk < BKK; kk += 8) {
            unsigned a[2][4];
#pragma unroll
            for (int mf = 0; mf < 2; mf++) {
                int ar = wm * 32 + mf * 16 + (lane >> 2);
                int ak = kk + (lane & 3);
                a[mf][0] = As[ar * 20 + ak];
                a[mf][1] = As[(ar + 8) * 20 + ak];
                a[mf][2] = As[ar * 20 + ak + 4];
                a[mf][3] = As[(ar + 8) * 20 + ak + 4];
            }
            unsigned b[4][2];
#pragma unroll
            for (int nf = 0; nf < 4; nf++) {
                int bn = wn * 32 + nf * 8 + (lane >> 2);
                int bk = kk + (lane & 3);
                b[nf][0] = Bs[bk * 72 + bn];
                b[nf][1] = Bs[(bk + 4) * 72 + bn];
            }
#pragma unroll
            for (int mf = 0; mf < 2; mf++)
#pragma unroll
                for (int nf = 0; nf < 4; nf++)
                    mma_tf32(acc[mf][nf], a[mf], b[nf]);
        }
    }

    // scatter-add into out
#pragma unroll
    for (int mf = 0; mf < 2; mf++) {
        int lr = wm * 32 + mf * 16 + (lane >> 2);
        int tlo = Ts[lr];
        int thi = Ts[lr + 8];
#pragma unroll
        for (int nf = 0; nf < 4; nf++) {
            int c = n0 + wn * 32 + nf * 8 + 2 * (lane & 3);
            if (tlo >= 0) {
                atomicAdd(&out[(size_t)tlo * D_ + c    ], acc[mf][nf][0]);
                atomicAdd(&out[(size_t)tlo * D_ + c + 1], acc[mf][nf][1]);
            }
            if (thi >= 0) {
                atomicAdd(&out[(size_t)thi * D_ + c    ], acc[mf][nf][2]);
                atomicAdd(&out[(size_t)thi * D_ + c + 1], acc[mf][nf][3]);
            }
        }
    }
}

__global__ void aux_k(float* __restrict__ out, long long out_size) {
    int lane = threadIdx.x;
    float v = (lane < E_) ? g_probs_sum[lane] * (float)g_cnt[lane] : 0.f;
#pragma unroll
    for (int off = 16; off; off >>= 1) v += __shfl_xor_sync(0xffffffffu, v, off);
    long long TD = (long long)T_ * D_;
    if (lane == 0 && out_size > TD)
        out[TD] = v / ((float)T_ * (float)T_);
}

// ---------------- launch ----------------
extern "C" void kernel_launch(void* const* d_in, const int* in_sizes, int n_in,
                              void* d_out, int out_size) {
    const float* x     = (const float*)d_in[0];
    const float* Wgate = (const float*)d_in[1];
    const float* Wg    = (const float*)d_in[2];
    const float* Wu    = (const float*)d_in[3];
    const float* Wd    = (const float*)d_in[4];
    float* out = (float*)d_out;

    cudaMemsetAsync(d_out, 0, (size_t)out_size * sizeof(float), 0);
    init_k<<<1, 32>>>();
    fill_k<<<CAP / 256, 256>>>();
    router_gemm_k<<<T_ / 64, 256>>>(x, Wgate);
    topk_k<<<T_ / 8, 256>>>();
    prefix_k<<<1, 1>>>();
    assign_k<<<(T_ * K_) / 256, 256>>>();
    gemm1_k<<<dim3(CAP / BM, I_ / BN), 256>>>(x, Wg, Wu);
    gemm2_k<<<dim3(CAP / BM, D_ / BN), 256>>>(Wd, out);
    aux_k<<<1, 32>>>(out, (long long)out_size);
}